// round 1
// baseline (speedup 1.0000x reference)
#include <cuda_runtime.h>
#include <math.h>
#include <stdint.h>

#define N_RAYS   32768
#define N_PLANES 32
#define NSAMP    (N_RAYS * N_PLANES)
#define EPSV     1e-8f
#define BM       128

// ---------------- scratch (device globals; no allocation allowed) ----------------
__device__ int   g_cnt;
__device__ int   g_sidx[NSAMP];          // compacted sample -> p*N+n
__device__ float g_world[NSAMP * 3];     // compacted world pos (hit only)
__device__ float g_vd[NSAMP * 3];        // compacted view dir (hit only)
__device__ float g_t[NSAMP];             // t for ALL samples (for sort/composite)
__device__ float g_rgba[NSAMP * 4];      // rgba for ALL samples (0 if not hit)
__device__ float g_h[NSAMP * 128];       // activation buffer (layer0 out, overwritten by layer1 out)

// ---------------- kernel 0: reset compaction counter ----------------
__global__ void k_reset() {
    if (threadIdx.x == 0) g_cnt = 0;
}

// ---------------- kernel 1: geometry + hit test + compaction ----------------
__global__ void __launch_bounds__(256) k_geom(
    const float* __restrict__ ndc, const float* __restrict__ cam_pos,
    const float* __restrict__ cam_R, const float* __restrict__ basis,
    const float* __restrict__ center, const float* __restrict__ wh)
{
    int gid = blockIdx.x * blockDim.x + threadIdx.x;
    if (gid >= NSAMP) return;
    int p = gid / N_RAYS;
    int n = gid - p * N_RAYS;

    float nd0 = ndc[n * 3 + 0], nd1 = ndc[n * 3 + 1], nd2 = ndc[n * 3 + 2];
    float d0 = cam_R[0] * nd0 + cam_R[1] * nd1 + cam_R[2] * nd2;
    float d1 = cam_R[3] * nd0 + cam_R[4] * nd1 + cam_R[5] * nd2;
    float d2 = cam_R[6] * nd0 + cam_R[7] * nd1 + cam_R[8] * nd2;
    float o0 = cam_pos[0], o1 = cam_pos[1], o2 = cam_pos[2];

    const float* B = basis + p * 9;
    float pn0 = B[2], pn1 = B[5], pn2 = B[8];   // basis[:, :, 2]
    float c0 = center[p * 3 + 0], c1 = center[p * 3 + 1], c2 = center[p * 3 + 2];

    float denom = pn0 * d0 + pn1 * d1 + pn2 * d2;
    if (fabsf(denom) < EPSV) denom = EPSV;
    float num = (c0 - o0) * pn0 + (c1 - o1) * pn1 + (c2 - o2) * pn2;
    float t = num / denom;

    float w0 = o0 + t * d0, w1 = o1 + t * d1, w2 = o2 + t * d2;
    float u = (w0 - c0) * B[0] + (w1 - c1) * B[3] + (w2 - c2) * B[6];
    float v = (w0 - c0) * B[1] + (w1 - c1) * B[4] + (w2 - c2) * B[7];
    bool inside = (fabsf(u) <= wh[p * 2 + 0] * 0.5f) && (fabsf(v) <= wh[p * 2 + 1] * 0.5f);
    bool hit = inside && (t > 0.0f);

    g_t[gid] = t;

    // warp-aggregated compaction
    unsigned mask = __ballot_sync(0xffffffffu, hit);
    if (hit) {
        int lane   = threadIdx.x & 31;
        int leader = __ffs(mask) - 1;
        int rank   = __popc(mask & ((1u << lane) - 1u));
        int base   = 0;
        if (lane == leader) base = atomicAdd(&g_cnt, __popc(mask));
        base = __shfl_sync(mask, base, leader);
        int i = base + rank;
        g_sidx[i] = gid;
        g_world[i * 3 + 0] = w0;
        g_world[i * 3 + 1] = w1;
        g_world[i * 3 + 2] = w2;
        float vd0 = w0 - o0, vd1 = w1 - o1, vd2 = w2 - o2;
        float inv = 1.0f / (sqrtf(vd0 * vd0 + vd1 * vd1 + vd2 * vd2) + EPSV);
        g_vd[i * 3 + 0] = vd0 * inv;
        g_vd[i * 3 + 1] = vd1 * inv;
        g_vd[i * 3 + 2] = vd2 * inv;
    } else {
        float4 z = make_float4(0.f, 0.f, 0.f, 0.f);
        *reinterpret_cast<float4*>(&g_rgba[gid * 4]) = z;
    }
}

// ---------------- kernel 2: positional encoding + layer0 (60->128, relu) ----------------
// dyn smem: As[128][64] (8192) | Bs[60][128] (7680) | bias[128]
#define SMEM_L0 ((128 * 64 + 60 * 128 + 128) * 4)
__global__ void __launch_bounds__(256) k_layer0(
    const float* __restrict__ W0, const float* __restrict__ b0)
{
    extern __shared__ float sm[];
    float* As   = sm;                   // [128][64], K padded 60->64
    float* Bs   = As + 128 * 64;        // [60][128]
    float* bias = Bs + 60 * 128;        // [128]

    int cnt = g_cnt;
    int m0  = blockIdx.x * BM;
    if (m0 >= cnt) return;
    int tid = threadIdx.x;

    for (int i = tid; i < 60 * 128; i += 256) Bs[i] = W0[i];
    if (tid < 128) bias[tid] = b0[tid];

    // build positional encoding tile: thread m handles one sample
    if (tid < 128) {
        int m = tid, gi = m0 + m;
        float* row = As + m * 64;
        if (gi < cnt) {
            #pragma unroll
            for (int c = 0; c < 3; c++) {
                float x = g_world[gi * 3 + c];
                float f = 1.0f;
                #pragma unroll
                for (int j = 0; j < 10; j++) {
                    float s, co;
                    sincosf(x * f, &s, &co);
                    row[c * 20 + j]      = s;
                    row[c * 20 + 10 + j] = co;
                    f *= 2.0f;
                }
            }
            row[60] = row[61] = row[62] = row[63] = 0.f;
        } else {
            #pragma unroll
            for (int k = 0; k < 64; k++) row[k] = 0.f;
        }
    }
    __syncthreads();

    int tm = (tid >> 4) << 3;   // 0..120
    int tn = (tid & 15) << 3;   // 0..120
    float acc[8][8];
    #pragma unroll
    for (int i = 0; i < 8; i++)
        #pragma unroll
        for (int j = 0; j < 8; j++) acc[i][j] = 0.f;

    for (int k = 0; k < 60; k++) {
        float a[8], b[8];
        #pragma unroll
        for (int i = 0; i < 8; i++) a[i] = As[(tm + i) * 64 + k];
        float4 b0v = *reinterpret_cast<const float4*>(&Bs[k * 128 + tn]);
        float4 b1v = *reinterpret_cast<const float4*>(&Bs[k * 128 + tn + 4]);
        b[0] = b0v.x; b[1] = b0v.y; b[2] = b0v.z; b[3] = b0v.w;
        b[4] = b1v.x; b[5] = b1v.y; b[6] = b1v.z; b[7] = b1v.w;
        #pragma unroll
        for (int i = 0; i < 8; i++)
            #pragma unroll
            for (int j = 0; j < 8; j++) acc[i][j] = fmaf(a[i], b[j], acc[i][j]);
    }

    #pragma unroll
    for (int i = 0; i < 8; i++) {
        int gi = m0 + tm + i;
        if (gi < cnt) {
            #pragma unroll
            for (int j = 0; j < 8; j++) {
                float h = acc[i][j] + bias[tn + j];
                g_h[gi * 128 + tn + j] = h > 0.f ? h : 0.f;
            }
        }
    }
}

// ---------------- kernel 3: layer1 (128->128, relu), in-place on g_h ----------------
// dyn smem: As[128][128] | Bs[128][128] | bias[128]
#define SMEM_L1 ((128 * 128 + 128 * 128 + 128) * 4)
__global__ void __launch_bounds__(256) k_layer1(
    const float* __restrict__ W1, const float* __restrict__ b1)
{
    extern __shared__ float sm[];
    float* As   = sm;                     // [128][128] row-major (m,k)
    float* Bs   = As + 128 * 128;         // [128][128]
    float* bias = Bs + 128 * 128;

    int cnt = g_cnt;
    int m0  = blockIdx.x * BM;
    if (m0 >= cnt) return;
    int tid = threadIdx.x;

    for (int i = tid; i < 128 * 128; i += 256) Bs[i] = W1[i];
    if (tid < 128) bias[tid] = b1[tid];

    for (int idx = tid; idx < 128 * 32; idx += 256) {
        int m = idx >> 5, k4 = idx & 31;
        int gi = m0 + m;
        float4 v = (gi < cnt) ? *reinterpret_cast<const float4*>(&g_h[gi * 128 + k4 * 4])
                              : make_float4(0.f, 0.f, 0.f, 0.f);
        *reinterpret_cast<float4*>(&As[m * 128 + k4 * 4]) = v;
    }
    __syncthreads();

    int tm = (tid >> 4) << 3;
    int tn = (tid & 15) << 3;
    float acc[8][8];
    #pragma unroll
    for (int i = 0; i < 8; i++)
        #pragma unroll
        for (int j = 0; j < 8; j++) acc[i][j] = 0.f;

    for (int k = 0; k < 128; k++) {
        float a[8], b[8];
        #pragma unroll
        for (int i = 0; i < 8; i++) a[i] = As[(tm + i) * 128 + k];
        float4 b0v = *reinterpret_cast<const float4*>(&Bs[k * 128 + tn]);
        float4 b1v = *reinterpret_cast<const float4*>(&Bs[k * 128 + tn + 4]);
        b[0] = b0v.x; b[1] = b0v.y; b[2] = b0v.z; b[3] = b0v.w;
        b[4] = b1v.x; b[5] = b1v.y; b[6] = b1v.z; b[7] = b1v.w;
        #pragma unroll
        for (int i = 0; i < 8; i++)
            #pragma unroll
            for (int j = 0; j < 8; j++) acc[i][j] = fmaf(a[i], b[j], acc[i][j]);
    }

    #pragma unroll
    for (int i = 0; i < 8; i++) {
        int gi = m0 + tm + i;
        if (gi < cnt) {
            #pragma unroll
            for (int j = 0; j < 8; j++) {
                float h = acc[i][j] + bias[tn + j];
                g_h[gi * 128 + tn + j] = h > 0.f ? h : 0.f;   // safe: tile fully staged in smem
            }
        }
    }
}

// ---------------- kernel 4: heads (alpha, color MLP) + scatter ----------------
// dyn smem: As[128][128] | Ad[128][24] | Wc1s[152][64] | hc[128][64] | Was[128] | alpha[128] | Wc2s[192] | bc1s[64]
#define SMEM_HD ((128 * 128 + 128 * 24 + 152 * 64 + 128 * 64 + 128 + 128 + 192 + 64) * 4)
__global__ void __launch_bounds__(256) k_heads(
    const float* __restrict__ Wa,  const float* __restrict__ ba,
    const float* __restrict__ Wc1, const float* __restrict__ bc1,
    const float* __restrict__ Wc2, const float* __restrict__ bc2)
{
    extern __shared__ float sm[];
    float* As    = sm;                        // [128][128]
    float* Ad    = As + 128 * 128;            // [128][24]
    float* Wc1s  = Ad + 128 * 24;             // [152][64]
    float* hc    = Wc1s + 152 * 64;           // [128][64]
    float* Was   = hc + 128 * 64;             // [128]
    float* alpha = Was + 128;                 // [128]
    float* Wc2s  = alpha + 128;               // [192]
    float* bc1s  = Wc2s + 192;                // [64]

    int cnt = g_cnt;
    int m0  = blockIdx.x * BM;
    if (m0 >= cnt) return;
    int tid = threadIdx.x;

    for (int i = tid; i < 152 * 64; i += 256) Wc1s[i] = Wc1[i];
    if (tid < 128) Was[tid] = Wa[tid];
    if (tid < 64)  bc1s[tid] = bc1[tid];
    if (tid < 192) Wc2s[tid] = Wc2[tid];

    for (int idx = tid; idx < 128 * 32; idx += 256) {
        int m = idx >> 5, k4 = idx & 31;
        int gi = m0 + m;
        float4 v = (gi < cnt) ? *reinterpret_cast<const float4*>(&g_h[gi * 128 + k4 * 4])
                              : make_float4(0.f, 0.f, 0.f, 0.f);
        *reinterpret_cast<float4*>(&As[m * 128 + k4 * 4]) = v;
    }

    // direction encoding (24 features), thread m = sample
    if (tid < 128) {
        int m = tid, gi = m0 + m;
        float* row = Ad + m * 24;
        if (gi < cnt) {
            #pragma unroll
            for (int c = 0; c < 3; c++) {
                float x = g_vd[gi * 3 + c];
                float f = 1.0f;
                #pragma unroll
                for (int j = 0; j < 4; j++) {
                    float s, co;
                    sincosf(x * f, &s, &co);
                    row[c * 8 + j]     = s;
                    row[c * 8 + 4 + j] = co;
                    f *= 2.0f;
                }
            }
        } else {
            #pragma unroll
            for (int k = 0; k < 24; k++) row[k] = 0.f;
        }
    }
    __syncthreads();

    // alpha = sigmoid(h @ Wa + ba)
    if (tid < 128) {
        float s = 0.f;
        #pragma unroll 4
        for (int k = 0; k < 128; k++) s = fmaf(As[tid * 128 + k], Was[k], s);
        alpha[tid] = 1.0f / (1.0f + expf(-(s + ba[0])));
    }

    // hc = relu([h | dir_enc] @ Wc1 + bc1)   (128x64, K=152)
    int tm = (tid >> 4) << 3;   // 0..120
    int tn = (tid & 15) << 2;   // 0..60
    float acc[8][4];
    #pragma unroll
    for (int i = 0; i < 8; i++)
        #pragma unroll
        for (int j = 0; j < 4; j++) acc[i][j] = 0.f;

    for (int k = 0; k < 128; k++) {
        float4 bv = *reinterpret_cast<const float4*>(&Wc1s[k * 64 + tn]);
        float b[4] = {bv.x, bv.y, bv.z, bv.w};
        #pragma unroll
        for (int i = 0; i < 8; i++) {
            float a = As[(tm + i) * 128 + k];
            #pragma unroll
            for (int j = 0; j < 4; j++) acc[i][j] = fmaf(a, b[j], acc[i][j]);
        }
    }
    for (int k = 0; k < 24; k++) {
        float4 bv = *reinterpret_cast<const float4*>(&Wc1s[(128 + k) * 64 + tn]);
        float b[4] = {bv.x, bv.y, bv.z, bv.w};
        #pragma unroll
        for (int i = 0; i < 8; i++) {
            float a = Ad[(tm + i) * 24 + k];
            #pragma unroll
            for (int j = 0; j < 4; j++) acc[i][j] = fmaf(a, b[j], acc[i][j]);
        }
    }
    #pragma unroll
    for (int i = 0; i < 8; i++)
        #pragma unroll
        for (int j = 0; j < 4; j++) {
            float h = acc[i][j] + bc1s[tn + j];
            hc[(tm + i) * 64 + tn + j] = h > 0.f ? h : 0.f;
        }
    __syncthreads();

    // rgb = sigmoid(hc @ Wc2 + bc2); scatter rgba
    if (tid < 128) {
        int m = tid, gi = m0 + m;
        if (gi < cnt) {
            float r0 = bc2[0], r1 = bc2[1], r2 = bc2[2];
            #pragma unroll 4
            for (int k = 0; k < 64; k++) {
                float h = hc[m * 64 + k];
                r0 = fmaf(h, Wc2s[k * 3 + 0], r0);
                r1 = fmaf(h, Wc2s[k * 3 + 1], r1);
                r2 = fmaf(h, Wc2s[k * 3 + 2], r2);
            }
            float4 outv;
            outv.x = 1.0f / (1.0f + expf(-r0));
            outv.y = 1.0f / (1.0f + expf(-r1));
            outv.z = 1.0f / (1.0f + expf(-r2));
            outv.w = alpha[m];
            int sid = g_sidx[gi];
            *reinterpret_cast<float4*>(&g_rgba[sid * 4]) = outv;
        }
    }
}

// ---------------- kernel 5: per-ray sort + alpha composite ----------------
__global__ void __launch_bounds__(256) k_composite(float* __restrict__ out)
{
    int n = blockIdx.x * blockDim.x + threadIdx.x;
    if (n >= N_RAYS) return;

    float tv[N_PLANES];
    int   pv[N_PLANES];
    #pragma unroll
    for (int p = 0; p < N_PLANES; p++) {
        tv[p] = g_t[p * N_RAYS + n];
        pv[p] = p;
    }
    // stable insertion sort ascending by t
    for (int i = 1; i < N_PLANES; i++) {
        float kt = tv[i];
        int   kp = pv[i];
        int j = i - 1;
        while (j >= 0 && tv[j] > kt) {
            tv[j + 1] = tv[j];
            pv[j + 1] = pv[j];
            j--;
        }
        tv[j + 1] = kt;
        pv[j + 1] = kp;
    }

    float trans = 1.0f, sw = 0.0f, depth = 0.0f;
    float c0 = 0.f, c1 = 0.f, c2 = 0.f;
    for (int s = 0; s < N_PLANES; s++) {
        int p = pv[s];
        float4 rg = *reinterpret_cast<const float4*>(&g_rgba[(p * N_RAYS + n) * 4]);
        float a = rg.w;
        float w = a * trans;
        depth = fmaf(tv[s], w, depth);
        c0 = fmaf(rg.x, w, c0);
        c1 = fmaf(rg.y, w, c1);
        c2 = fmaf(rg.z, w, c2);
        sw += w;
        trans *= (1.0f - a);
    }
    float bg = 1.0f - sw;
    out[n * 4 + 0] = c0 + bg;
    out[n * 4 + 1] = c1 + bg;
    out[n * 4 + 2] = c2 + bg;
    out[n * 4 + 3] = depth;
}

// ---------------- launch ----------------
extern "C" void kernel_launch(void* const* d_in, const int* in_sizes, int n_in,
                              void* d_out, int out_size)
{
    const float* ndc    = (const float*)d_in[0];
    const float* campos = (const float*)d_in[1];
    const float* camR   = (const float*)d_in[2];
    const float* basis  = (const float*)d_in[3];
    const float* center = (const float*)d_in[4];
    const float* wh     = (const float*)d_in[5];
    const float* W0     = (const float*)d_in[6];
    const float* b0     = (const float*)d_in[7];
    const float* W1     = (const float*)d_in[8];
    const float* b1     = (const float*)d_in[9];
    const float* Wa     = (const float*)d_in[10];
    const float* ba     = (const float*)d_in[11];
    const float* Wc1    = (const float*)d_in[12];
    const float* bc1    = (const float*)d_in[13];
    const float* Wc2    = (const float*)d_in[14];
    const float* bc2    = (const float*)d_in[15];
    float* out = (float*)d_out;

    cudaFuncSetAttribute(k_layer0, cudaFuncAttributeMaxDynamicSharedMemorySize, SMEM_L0);
    cudaFuncSetAttribute(k_layer1, cudaFuncAttributeMaxDynamicSharedMemorySize, SMEM_L1);
    cudaFuncSetAttribute(k_heads,  cudaFuncAttributeMaxDynamicSharedMemorySize, SMEM_HD);

    k_reset<<<1, 32>>>();
    k_geom<<<NSAMP / 256, 256>>>(ndc, campos, camR, basis, center, wh);

    int nTiles = (NSAMP + BM - 1) / BM;   // worst case; tiles past g_cnt exit immediately
    k_layer0<<<nTiles, 256, SMEM_L0>>>(W0, b0);
    k_layer1<<<nTiles, 256, SMEM_L1>>>(W1, b1);
    k_heads <<<nTiles, 256, SMEM_HD>>>(Wa, ba, Wc1, bc1, Wc2, bc2);

    k_composite<<<(N_RAYS + 255) / 256, 256>>>(out);
}

// round 3
// speedup vs baseline: 1.5498x; 1.5498x over previous
#include <cuda_runtime.h>
#include <math.h>
#include <stdint.h>

#define N_RAYS   32768
#define N_PLANES 32
#define NSAMP    (N_RAYS * N_PLANES)
#define EPSV     1e-8f
#define BM       128
#define PERSIST_BLOCKS 148

// ---------------- scratch (device globals; no allocation allowed) ----------------
__device__ int   g_cnt;
__device__ int   g_sidx[NSAMP];          // compacted sample -> p*N+n
__device__ float g_world[NSAMP * 3];     // compacted world pos (hit only)
__device__ float g_vd[NSAMP * 3];        // compacted view dir (hit only)
__device__ float g_t[NSAMP];             // t for ALL samples
__device__ float g_rgba[NSAMP * 4];      // rgba for ALL samples (0 if not hit)

// ---------------- kernel 0: reset compaction counter ----------------
__global__ void k_reset() {
    if (threadIdx.x == 0) g_cnt = 0;
}

// ---------------- kernel 1: geometry + hit test + compaction ----------------
__global__ void __launch_bounds__(256) k_geom(
    const float* __restrict__ ndc, const float* __restrict__ cam_pos,
    const float* __restrict__ cam_R, const float* __restrict__ basis,
    const float* __restrict__ center, const float* __restrict__ wh)
{
    int gid = blockIdx.x * blockDim.x + threadIdx.x;
    if (gid >= NSAMP) return;
    int p = gid / N_RAYS;
    int n = gid - p * N_RAYS;

    float nd0 = ndc[n * 3 + 0], nd1 = ndc[n * 3 + 1], nd2 = ndc[n * 3 + 2];
    float d0 = cam_R[0] * nd0 + cam_R[1] * nd1 + cam_R[2] * nd2;
    float d1 = cam_R[3] * nd0 + cam_R[4] * nd1 + cam_R[5] * nd2;
    float d2 = cam_R[6] * nd0 + cam_R[7] * nd1 + cam_R[8] * nd2;
    float o0 = cam_pos[0], o1 = cam_pos[1], o2 = cam_pos[2];

    const float* B = basis + p * 9;
    float pn0 = B[2], pn1 = B[5], pn2 = B[8];   // basis[:, :, 2]
    float c0 = center[p * 3 + 0], c1 = center[p * 3 + 1], c2 = center[p * 3 + 2];

    float denom = pn0 * d0 + pn1 * d1 + pn2 * d2;
    if (fabsf(denom) < EPSV) denom = EPSV;
    float num = (c0 - o0) * pn0 + (c1 - o1) * pn1 + (c2 - o2) * pn2;
    float t = num / denom;

    float w0 = o0 + t * d0, w1 = o1 + t * d1, w2 = o2 + t * d2;
    float u = (w0 - c0) * B[0] + (w1 - c1) * B[3] + (w2 - c2) * B[6];
    float v = (w0 - c0) * B[1] + (w1 - c1) * B[4] + (w2 - c2) * B[7];
    bool inside = (fabsf(u) <= wh[p * 2 + 0] * 0.5f) && (fabsf(v) <= wh[p * 2 + 1] * 0.5f);
    bool hit = inside && (t > 0.0f);

    g_t[gid] = t;

    unsigned mask = __ballot_sync(0xffffffffu, hit);
    if (hit) {
        int lane   = threadIdx.x & 31;
        int leader = __ffs(mask) - 1;
        int rank   = __popc(mask & ((1u << lane) - 1u));
        int base   = 0;
        if (lane == leader) base = atomicAdd(&g_cnt, __popc(mask));
        base = __shfl_sync(mask, base, leader);
        int i = base + rank;
        g_sidx[i] = gid;
        g_world[i * 3 + 0] = w0;
        g_world[i * 3 + 1] = w1;
        g_world[i * 3 + 2] = w2;
        float vd0 = w0 - o0, vd1 = w1 - o1, vd2 = w2 - o2;
        float inv = 1.0f / (sqrtf(vd0 * vd0 + vd1 * vd1 + vd2 * vd2) + EPSV);
        g_vd[i * 3 + 0] = vd0 * inv;
        g_vd[i * 3 + 1] = vd1 * inv;
        g_vd[i * 3 + 2] = vd2 * inv;
    } else {
        float4 z = make_float4(0.f, 0.f, 0.f, 0.f);
        *reinterpret_cast<float4*>(&g_rgba[gid * 4]) = z;
    }
}

// ---------------- fused persistent MLP kernel ----------------
// smem floats: A[128*128] | B[128*128] | W[128*128] | Denc[128*24]
//              | bias[128] | Was[128] | alpha[128] | Wc2s[192] | bc1s[64]
#define SMEM_F ((128*128*3 + 128*24 + 128 + 128 + 128 + 192 + 64) * 4)

__global__ void __launch_bounds__(256, 1) k_mlp(
    const float* __restrict__ W0,  const float* __restrict__ b0,
    const float* __restrict__ W1,  const float* __restrict__ b1,
    const float* __restrict__ Wa,  const float* __restrict__ ba,
    const float* __restrict__ Wc1, const float* __restrict__ bc1,
    const float* __restrict__ Wc2, const float* __restrict__ bc2)
{
    extern __shared__ float sm[];
    float* As    = sm;                 // ping: encode uses stride 65, layer1 out stride 128
    float* Bs    = As + 128 * 128;     // pong: layer0 out (128), hc (stride 64)
    float* Ws    = Bs + 128 * 128;     // weight staging
    float* Denc  = Ws + 128 * 128;     // [128][24]
    float* bias  = Denc + 128 * 24;    // [128]
    float* Was   = bias + 128;
    float* alpha = Was + 128;
    float* Wc2s  = alpha + 128;        // [192]
    float* bc1s  = Wc2s + 192;         // [64]

    const int cnt    = g_cnt;
    const int nTiles = (cnt + BM - 1) >> 7;
    const int tid    = threadIdx.x;
    const int lane   = tid & 31;
    const int m      = tid & 127;      // sample within tile (for per-sample work)
    const int half   = tid >> 7;       // 0/1 split of encoding work
    const int tm     = (tid >> 4) << 3;
    const int tn8    = (tid & 15) << 3;
    const int tn4    = (tid & 15) << 2;
    const float ba0  = ba[0];
    const float bc20 = bc2[0], bc21 = bc2[1], bc22 = bc2[2];

    // load small persistent weights once
    if (tid < 128) Was[tid]  = Wa[tid];
    if (tid < 192) Wc2s[tid] = Wc2[tid];
    if (tid < 64)  bc1s[tid] = bc1[tid];

    for (int tile = blockIdx.x; tile < nTiles; tile += gridDim.x) {
        int m0 = tile << 7;
        int gi = m0 + m;

        // ---- S1: positional encoding into As (row stride 65) + stage W0 ----
        {
            float* row = As + m * 65;
            if (gi < cnt) {
                const float* wp = &g_world[gi * 3];
                if (half == 0) {
                    float x = wp[0], f = 1.f;
                    #pragma unroll
                    for (int j = 0; j < 10; j++) {
                        float s, c; sincosf(x * f, &s, &c);
                        row[j] = s; row[10 + j] = c; f *= 2.f;
                    }
                    x = wp[2]; f = 1.f;
                    #pragma unroll
                    for (int j = 0; j < 5; j++) {
                        float s, c; sincosf(x * f, &s, &c);
                        row[40 + j] = s; row[50 + j] = c; f *= 2.f;
                    }
                } else {
                    float x = wp[1], f = 1.f;
                    #pragma unroll
                    for (int j = 0; j < 10; j++) {
                        float s, c; sincosf(x * f, &s, &c);
                        row[20 + j] = s; row[30 + j] = c; f *= 2.f;
                    }
                    x = wp[2]; f = 32.f;
                    #pragma unroll
                    for (int j = 0; j < 5; j++) {
                        float s, c; sincosf(x * f, &s, &c);
                        row[45 + j] = s; row[55 + j] = c; f *= 2.f;
                    }
                }
            } else {
                #pragma unroll
                for (int k = half * 30; k < half * 30 + 30; k++) row[k] = 0.f;
            }
        }
        for (int i = tid; i < 60 * 128 / 4; i += 256)
            reinterpret_cast<float4*>(Ws)[i] = reinterpret_cast<const float4*>(W0)[i];
        if (tid < 128) bias[tid] = b0[tid];
        __syncthreads();

        // ---- S2: Bs = relu(As(128x60,ld65) @ W0 + b0) ----
        {
            float acc[8][8];
            #pragma unroll
            for (int i = 0; i < 8; i++)
                #pragma unroll
                for (int j = 0; j < 8; j++) acc[i][j] = 0.f;
            for (int k = 0; k < 60; k++) {
                float a[8], b[8];
                #pragma unroll
                for (int i = 0; i < 8; i++) a[i] = As[(tm + i) * 65 + k];
                float4 bv0 = *reinterpret_cast<const float4*>(&Ws[k * 128 + tn8]);
                float4 bv1 = *reinterpret_cast<const float4*>(&Ws[k * 128 + tn8 + 4]);
                b[0]=bv0.x; b[1]=bv0.y; b[2]=bv0.z; b[3]=bv0.w;
                b[4]=bv1.x; b[5]=bv1.y; b[6]=bv1.z; b[7]=bv1.w;
                #pragma unroll
                for (int i = 0; i < 8; i++)
                    #pragma unroll
                    for (int j = 0; j < 8; j++) acc[i][j] = fmaf(a[i], b[j], acc[i][j]);
            }
            #pragma unroll
            for (int i = 0; i < 8; i++)
                #pragma unroll
                for (int j = 0; j < 8; j++) {
                    float h = acc[i][j] + bias[tn8 + j];
                    Bs[(tm + i) * 128 + tn8 + j] = h > 0.f ? h : 0.f;
                }
        }
        __syncthreads();

        // ---- stage W1 ----
        for (int i = tid; i < 128 * 128 / 4; i += 256)
            reinterpret_cast<float4*>(Ws)[i] = reinterpret_cast<const float4*>(W1)[i];
        if (tid < 128) bias[tid] = b1[tid];
        __syncthreads();

        // ---- S3: As = relu(Bs @ W1 + b1), stride 128 ----
        {
            float acc[8][8];
            #pragma unroll
            for (int i = 0; i < 8; i++)
                #pragma unroll
                for (int j = 0; j < 8; j++) acc[i][j] = 0.f;
            for (int k = 0; k < 128; k++) {
                float a[8], b[8];
                #pragma unroll
                for (int i = 0; i < 8; i++) a[i] = Bs[(tm + i) * 128 + k];
                float4 bv0 = *reinterpret_cast<const float4*>(&Ws[k * 128 + tn8]);
                float4 bv1 = *reinterpret_cast<const float4*>(&Ws[k * 128 + tn8 + 4]);
                b[0]=bv0.x; b[1]=bv0.y; b[2]=bv0.z; b[3]=bv0.w;
                b[4]=bv1.x; b[5]=bv1.y; b[6]=bv1.z; b[7]=bv1.w;
                #pragma unroll
                for (int i = 0; i < 8; i++)
                    #pragma unroll
                    for (int j = 0; j < 8; j++) acc[i][j] = fmaf(a[i], b[j], acc[i][j]);
            }
            #pragma unroll
            for (int i = 0; i < 8; i++)
                #pragma unroll
                for (int j = 0; j < 8; j++) {
                    float h = acc[i][j] + bias[tn8 + j];
                    As[(tm + i) * 128 + tn8 + j] = h > 0.f ? h : 0.f;
                }
        }
        __syncthreads();

        // ---- S4: alpha, dir-encode, stage Wc1 ----
        for (int i = tid; i < 152 * 64 / 4; i += 256)
            reinterpret_cast<float4*>(Ws)[i] = reinterpret_cast<const float4*>(Wc1)[i];
        if (tid < 128) {
            float s = 0.f;
            const float* arow = As + tid * 128;
            #pragma unroll 4
            for (int k = 0; k < 128; k++) {
                int k2 = (k + lane) & 127;           // lane-rotated: conflict-free
                s = fmaf(arow[k2], Was[k2], s);
            }
            alpha[tid] = 1.0f / (1.0f + expf(-(s + ba0)));
        }
        {
            float* row = Denc + m * 24;
            if (gi < cnt) {
                const float* vp = &g_vd[gi * 3];
                if (half == 0) {
                    float x = vp[0], f = 1.f;
                    #pragma unroll
                    for (int j = 0; j < 4; j++) {
                        float s, c; sincosf(x * f, &s, &c);
                        row[j] = s; row[4 + j] = c; f *= 2.f;
                    }
                    x = vp[2]; f = 1.f;
                    #pragma unroll
                    for (int j = 0; j < 2; j++) {
                        float s, c; sincosf(x * f, &s, &c);
                        row[16 + j] = s; row[20 + j] = c; f *= 2.f;
                    }
                } else {
                    float x = vp[1], f = 1.f;
                    #pragma unroll
                    for (int j = 0; j < 4; j++) {
                        float s, c; sincosf(x * f, &s, &c);
                        row[8 + j] = s; row[12 + j] = c; f *= 2.f;
                    }
                    x = vp[2]; f = 4.f;
                    #pragma unroll
                    for (int j = 0; j < 2; j++) {
                        float s, c; sincosf(x * f, &s, &c);
                        row[18 + j] = s; row[22 + j] = c; f *= 2.f;
                    }
                }
            } else {
                #pragma unroll
                for (int k = half * 12; k < half * 12 + 12; k++) row[k] = 0.f;
            }
        }
        __syncthreads();

        // ---- S5: hc = relu([As | Denc] @ Wc1 + bc1) -> Bs (stride 64) ----
        {
            float acc[8][4];
            #pragma unroll
            for (int i = 0; i < 8; i++)
                #pragma unroll
                for (int j = 0; j < 4; j++) acc[i][j] = 0.f;
            for (int k = 0; k < 128; k++) {
                float4 bv = *reinterpret_cast<const float4*>(&Ws[k * 64 + tn4]);
                float b[4] = {bv.x, bv.y, bv.z, bv.w};
                #pragma unroll
                for (int i = 0; i < 8; i++) {
                    float a = As[(tm + i) * 128 + k];
                    #pragma unroll
                    for (int j = 0; j < 4; j++) acc[i][j] = fmaf(a, b[j], acc[i][j]);
                }
            }
            for (int k = 0; k < 24; k++) {
                float4 bv = *reinterpret_cast<const float4*>(&Ws[(128 + k) * 64 + tn4]);
                float b[4] = {bv.x, bv.y, bv.z, bv.w};
                #pragma unroll
                for (int i = 0; i < 8; i++) {
                    float a = Denc[(tm + i) * 24 + k];
                    #pragma unroll
                    for (int j = 0; j < 4; j++) acc[i][j] = fmaf(a, b[j], acc[i][j]);
                }
            }
            #pragma unroll
            for (int i = 0; i < 8; i++)
                #pragma unroll
                for (int j = 0; j < 4; j++) {
                    float h = acc[i][j] + bc1s[tn4 + j];
                    Bs[(tm + i) * 64 + tn4 + j] = h > 0.f ? h : 0.f;
                }
        }
        __syncthreads();

        // ---- S6: rgb = sigmoid(hc @ Wc2 + bc2); scatter rgba ----
        if (tid < 128 && gi < cnt) {
            float r0 = bc20, r1 = bc21, r2 = bc22;
            const float* hrow = Bs + m * 64;
            #pragma unroll 4
            for (int k = 0; k < 64; k++) {
                int k2 = (k + lane) & 63;            // lane-rotated: conflict-free
                float h = hrow[k2];
                r0 = fmaf(h, Wc2s[k2 * 3 + 0], r0);
                r1 = fmaf(h, Wc2s[k2 * 3 + 1], r1);
                r2 = fmaf(h, Wc2s[k2 * 3 + 2], r2);
            }
            float4 outv;
            outv.x = 1.0f / (1.0f + expf(-r0));
            outv.y = 1.0f / (1.0f + expf(-r1));
            outv.z = 1.0f / (1.0f + expf(-r2));
            outv.w = alpha[m];
            *reinterpret_cast<float4*>(&g_rgba[g_sidx[gi] * 4]) = outv;
        }
        __syncthreads();   // protect As/Bs/Ws before next tile overwrites
    }
}

// ---------------- kernel 5: per-ray sort + alpha composite ----------------
__global__ void __launch_bounds__(256) k_composite(float* __restrict__ out)
{
    int n = blockIdx.x * blockDim.x + threadIdx.x;
    if (n >= N_RAYS) return;

    float tv[N_PLANES];
    int   pv[N_PLANES];
    #pragma unroll
    for (int p = 0; p < N_PLANES; p++) {
        tv[p] = g_t[p * N_RAYS + n];
        pv[p] = p;
    }
    for (int i = 1; i < N_PLANES; i++) {
        float kt = tv[i];
        int   kp = pv[i];
        int j = i - 1;
        while (j >= 0 && tv[j] > kt) {
            tv[j + 1] = tv[j];
            pv[j + 1] = pv[j];
            j--;
        }
        tv[j + 1] = kt;
        pv[j + 1] = kp;
    }

    float trans = 1.0f, sw = 0.0f, depth = 0.0f;
    float c0 = 0.f, c1 = 0.f, c2 = 0.f;
    for (int s = 0; s < N_PLANES; s++) {
        int p = pv[s];
        float4 rg = *reinterpret_cast<const float4*>(&g_rgba[(p * N_RAYS + n) * 4]);
        float a = rg.w;
        float w = a * trans;
        depth = fmaf(tv[s], w, depth);
        c0 = fmaf(rg.x, w, c0);
        c1 = fmaf(rg.y, w, c1);
        c2 = fmaf(rg.z, w, c2);
        sw += w;
        trans *= (1.0f - a);
    }
    float bg = 1.0f - sw;
    out[n * 4 + 0] = c0 + bg;
    out[n * 4 + 1] = c1 + bg;
    out[n * 4 + 2] = c2 + bg;
    out[n * 4 + 3] = depth;
}

// ---------------- launch ----------------
extern "C" void kernel_launch(void* const* d_in, const int* in_sizes, int n_in,
                              void* d_out, int out_size)
{
    const float* ndc    = (const float*)d_in[0];
    const float* campos = (const float*)d_in[1];
    const float* camR   = (const float*)d_in[2];
    const float* basis  = (const float*)d_in[3];
    const float* center = (const float*)d_in[4];
    const float* wh     = (const float*)d_in[5];
    const float* W0     = (const float*)d_in[6];
    const float* b0     = (const float*)d_in[7];
    const float* W1     = (const float*)d_in[8];
    const float* b1     = (const float*)d_in[9];
    const float* Wa     = (const float*)d_in[10];
    const float* ba     = (const float*)d_in[11];
    const float* Wc1    = (const float*)d_in[12];
    const float* bc1    = (const float*)d_in[13];
    const float* Wc2    = (const float*)d_in[14];
    const float* bc2    = (const float*)d_in[15];
    float* out = (float*)d_out;

    static int smem_set = 0;
    if (!smem_set) {
        cudaFuncSetAttribute(k_mlp, cudaFuncAttributeMaxDynamicSharedMemorySize, SMEM_F);
        smem_set = 1;
    }

    k_reset<<<1, 32>>>();
    k_geom<<<NSAMP / 256, 256>>>(ndc, campos, camR, basis, center, wh);
    k_mlp<<<PERSIST_BLOCKS, 256, SMEM_F>>>(W0, b0, W1, b1, Wa, ba, Wc1, bc1, Wc2, bc2);
    k_composite<<<(N_RAYS + 255) / 256, 256>>>(out);
}

// round 6
// speedup vs baseline: 1.5736x; 1.0154x over previous
#include <cuda_runtime.h>
#include <math.h>
#include <stdint.h>

#define N_RAYS   32768
#define N_PLANES 32
#define NSAMP    (N_RAYS * N_PLANES)
#define EPSV     1e-8f
#define BM       64
#define PERSIST_BLOCKS 148

typedef unsigned long long ull;

// ---------------- scratch ----------------
__device__ int   g_cnt;
__device__ int   g_sidx[NSAMP];
__device__ float g_world[NSAMP * 3];
__device__ float g_vd[NSAMP * 3];
__device__ float g_t[NSAMP];
__device__ float g_rgba[NSAMP * 4];

// ---------------- f32x2 helpers ----------------
__device__ __forceinline__ ull pack2(float lo, float hi) {
    ull r; asm("mov.b64 %0, {%1, %2};" : "=l"(r) : "f"(lo), "f"(hi)); return r;
}
__device__ __forceinline__ float2 unpack2(ull v) {
    float2 r; asm("mov.b64 {%0, %1}, %2;" : "=f"(r.x), "=f"(r.y) : "l"(v)); return r;
}
__device__ __forceinline__ void fma2(ull& d, ull a, ull b) {
    asm("fma.rn.f32x2 %0, %1, %2, %3;" : "=l"(d) : "l"(a), "l"(b), "l"(d));
}

// ---------------- kernel 0 ----------------
__global__ void k_reset() { if (threadIdx.x == 0) g_cnt = 0; }

// ---------------- kernel 1: geometry + compaction ----------------
__global__ void __launch_bounds__(256) k_geom(
    const float* __restrict__ ndc, const float* __restrict__ cam_pos,
    const float* __restrict__ cam_R, const float* __restrict__ basis,
    const float* __restrict__ center, const float* __restrict__ wh)
{
    int gid = blockIdx.x * blockDim.x + threadIdx.x;
    if (gid >= NSAMP) return;
    int p = gid / N_RAYS;
    int n = gid - p * N_RAYS;

    float nd0 = ndc[n * 3 + 0], nd1 = ndc[n * 3 + 1], nd2 = ndc[n * 3 + 2];
    float d0 = cam_R[0] * nd0 + cam_R[1] * nd1 + cam_R[2] * nd2;
    float d1 = cam_R[3] * nd0 + cam_R[4] * nd1 + cam_R[5] * nd2;
    float d2 = cam_R[6] * nd0 + cam_R[7] * nd1 + cam_R[8] * nd2;
    float o0 = cam_pos[0], o1 = cam_pos[1], o2 = cam_pos[2];

    const float* B = basis + p * 9;
    float pn0 = B[2], pn1 = B[5], pn2 = B[8];
    float c0 = center[p * 3 + 0], c1 = center[p * 3 + 1], c2 = center[p * 3 + 2];

    float denom = pn0 * d0 + pn1 * d1 + pn2 * d2;
    if (fabsf(denom) < EPSV) denom = EPSV;
    float num = (c0 - o0) * pn0 + (c1 - o1) * pn1 + (c2 - o2) * pn2;
    float t = num / denom;

    float w0 = o0 + t * d0, w1 = o1 + t * d1, w2 = o2 + t * d2;
    float u = (w0 - c0) * B[0] + (w1 - c1) * B[3] + (w2 - c2) * B[6];
    float v = (w0 - c0) * B[1] + (w1 - c1) * B[4] + (w2 - c2) * B[7];
    bool inside = (fabsf(u) <= wh[p * 2 + 0] * 0.5f) && (fabsf(v) <= wh[p * 2 + 1] * 0.5f);
    bool hit = inside && (t > 0.0f);

    g_t[gid] = t;

    unsigned mask = __ballot_sync(0xffffffffu, hit);
    if (hit) {
        int lane   = threadIdx.x & 31;
        int leader = __ffs(mask) - 1;
        int rank   = __popc(mask & ((1u << lane) - 1u));
        int base   = 0;
        if (lane == leader) base = atomicAdd(&g_cnt, __popc(mask));
        base = __shfl_sync(mask, base, leader);
        int i = base + rank;
        g_sidx[i] = gid;
        g_world[i * 3 + 0] = w0;
        g_world[i * 3 + 1] = w1;
        g_world[i * 3 + 2] = w2;
        float vd0 = w0 - o0, vd1 = w1 - o1, vd2 = w2 - o2;
        float inv = 1.0f / (sqrtf(vd0 * vd0 + vd1 * vd1 + vd2 * vd2) + EPSV);
        g_vd[i * 3 + 0] = vd0 * inv;
        g_vd[i * 3 + 1] = vd1 * inv;
        g_vd[i * 3 + 2] = vd2 * inv;
    } else {
        float4 z = make_float4(0.f, 0.f, 0.f, 0.f);
        *reinterpret_cast<float4*>(&g_rgba[gid * 4]) = z;
    }
}

// ---------------- fused persistent MLP ----------------
#define OFF_W0    0
#define OFF_W1    (OFF_W0 + 60 * 128)
#define OFF_WC1   (OFF_W1 + 128 * 128)
#define OFF_A     (OFF_WC1 + 152 * 64)
#define OFF_B     (OFF_A + 64 * 132)
#define OFF_DENC  (OFF_B + 64 * 132)
#define OFF_BIAS0 (OFF_DENC + 64 * 28)
#define OFF_BIAS1 (OFF_BIAS0 + 128)
#define OFF_WAS   (OFF_BIAS1 + 128)
#define OFF_WC2   (OFF_WAS + 128)
#define OFF_BC1   (OFF_WC2 + 192)
#define OFF_ALPHA (OFF_BC1 + 64)
#define SMEM_TOT  (OFF_ALPHA + 64)
#define SMEM_F    (SMEM_TOT * 4)

#define ACT_LD 132
#define ENC_LD 68
#define HC_LD  68
#define DENC_LD 28

// 64x128 GEMM: A[64xK] (lda), B[Kx128] (ld 128), relu(x+bias) -> D[64x128] (ldd)
__device__ __forceinline__ void gemm_128(
    const float* __restrict__ A, int lda,
    const float* __restrict__ B, const float* __restrict__ bias,
    float* __restrict__ D, int ldd, int K, int tid)
{
    int R = (tid >> 4) << 2;       // 0..60
    int C = (tid & 15) << 3;       // 0..120
    ull acc[4][4];
    #pragma unroll
    for (int i = 0; i < 4; i++)
        #pragma unroll
        for (int j = 0; j < 4; j++) acc[i][j] = 0ull;

    #pragma unroll 2
    for (int k = 0; k < K; k++) {
        ull ap[4];
        #pragma unroll
        for (int i = 0; i < 4; i++) {
            float a = A[(R + i) * lda + k];
            ap[i] = pack2(a, a);
        }
        ulonglong2 bv0 = *reinterpret_cast<const ulonglong2*>(&B[k * 128 + C]);
        ulonglong2 bv1 = *reinterpret_cast<const ulonglong2*>(&B[k * 128 + C + 4]);
        ull bp[4] = {bv0.x, bv0.y, bv1.x, bv1.y};
        #pragma unroll
        for (int i = 0; i < 4; i++)
            #pragma unroll
            for (int j = 0; j < 4; j++) fma2(acc[i][j], ap[i], bp[j]);
    }
    #pragma unroll
    for (int i = 0; i < 4; i++)
        #pragma unroll
        for (int j = 0; j < 4; j++) {
            float2 v = unpack2(acc[i][j]);
            float lo = v.x + bias[C + 2 * j];
            float hi = v.y + bias[C + 2 * j + 1];
            lo = lo > 0.f ? lo : 0.f;
            hi = hi > 0.f ? hi : 0.f;
            *reinterpret_cast<float2*>(&D[(R + i) * ldd + C + 2 * j]) = make_float2(lo, hi);
        }
}

__global__ void __launch_bounds__(256, 1) k_mlp(
    const float* __restrict__ W0,  const float* __restrict__ b0,
    const float* __restrict__ W1,  const float* __restrict__ b1,
    const float* __restrict__ Wa,  const float* __restrict__ ba,
    const float* __restrict__ Wc1, const float* __restrict__ bc1,
    const float* __restrict__ Wc2, const float* __restrict__ bc2)
{
    extern __shared__ float sm[];
    float* W0s   = sm + OFF_W0;
    float* W1s   = sm + OFF_W1;
    float* Wc1s  = sm + OFF_WC1;
    float* As    = sm + OFF_A;
    float* Bs    = sm + OFF_B;
    float* Denc  = sm + OFF_DENC;
    float* bias0 = sm + OFF_BIAS0;
    float* bias1 = sm + OFF_BIAS1;
    float* Was   = sm + OFF_WAS;
    float* Wc2s  = sm + OFF_WC2;
    float* bc1s  = sm + OFF_BC1;
    float* alpha = sm + OFF_ALPHA;

    const int cnt    = g_cnt;
    const int nTiles = (cnt + BM - 1) >> 6;
    const int tid    = threadIdx.x;
    const int lane   = tid & 31;
    const int ms     = tid >> 2;     // sample for 4-way encode split (0..63)
    const int q      = tid & 3;      // quarter of encode work
    const float ba0  = ba[0];
    const float bc20 = bc2[0], bc21 = bc2[1], bc22 = bc2[2];

    // ---- one-time weight staging ----
    for (int i = tid; i < 60 * 128 / 4; i += 256)
        reinterpret_cast<float4*>(W0s)[i] = reinterpret_cast<const float4*>(W0)[i];
    for (int i = tid; i < 128 * 128 / 4; i += 256)
        reinterpret_cast<float4*>(W1s)[i] = reinterpret_cast<const float4*>(W1)[i];
    for (int i = tid; i < 152 * 64 / 4; i += 256)
        reinterpret_cast<float4*>(Wc1s)[i] = reinterpret_cast<const float4*>(Wc1)[i];
    if (tid < 128) { bias0[tid] = b0[tid]; bias1[tid] = b1[tid]; Was[tid] = Wa[tid]; }
    if (tid < 192) Wc2s[tid] = Wc2[tid];
    if (tid < 64)  bc1s[tid] = bc1[tid];
    __syncthreads();

    for (int tile = blockIdx.x; tile < nTiles; tile += gridDim.x) {
        const int m0  = tile << 6;
        const int gie = m0 + ms;    // sample index for encode stages (4 threads each)

        // ---- S1: positional encoding into As (stride ENC_LD), 4 threads/sample ----
        {
            float* row = As + ms * ENC_LD;
            if (gie < cnt) {
                const float* wp = &g_world[gie * 3];
                float x0 = wp[0], x1 = wp[1], x2 = wp[2];
                for (int u = q; u < 30; u += 4) {
                    int c = (u >= 20) ? 2 : (u >= 10 ? 1 : 0);
                    int j = u - c * 10;
                    float x = (c == 0) ? x0 : (c == 1 ? x1 : x2);
                    float s, co;
                    sincosf(x * (float)(1 << j), &s, &co);
                    row[c * 20 + j]      = s;
                    row[c * 20 + 10 + j] = co;
                }
            } else {
                for (int u = q; u < 30; u += 4) {
                    int c = (u >= 20) ? 2 : (u >= 10 ? 1 : 0);
                    int j = u - c * 10;
                    row[c * 20 + j] = 0.f;
                    row[c * 20 + 10 + j] = 0.f;
                }
            }
        }
        __syncthreads();

        // ---- S2: Bs = relu(enc @ W0 + b0) ----
        gemm_128(As, ENC_LD, W0s, bias0, Bs, ACT_LD, 60, tid);
        __syncthreads();

        // ---- S3: As = relu(Bs @ W1 + b1) ----
        gemm_128(Bs, ACT_LD, W1s, bias1, As, ACT_LD, 128, tid);
        __syncthreads();

        // ---- S4: alpha (tid<64, sample=tid) + dir encoding (4 threads/sample ms) ----
        if (tid < 64) {
            float s = 0.f;
            const float* arow = As + tid * ACT_LD;
            #pragma unroll 4
            for (int k = 0; k < 128; k++) {
                int k2 = (k + lane) & 127;
                s = fmaf(arow[k2], Was[k2], s);
            }
            alpha[tid] = 1.0f / (1.0f + expf(-(s + ba0)));
        }
        {
            float* row = Denc + ms * DENC_LD;
            if (gie < cnt) {
                const float* vp = &g_vd[gie * 3];
                float x0 = vp[0], x1 = vp[1], x2 = vp[2];
                for (int u = q; u < 12; u += 4) {
                    int c = u >> 2;
                    int j = u & 3;
                    float x = (c == 0) ? x0 : (c == 1 ? x1 : x2);
                    float s, co;
                    sincosf(x * (float)(1 << j), &s, &co);
                    row[c * 8 + j]     = s;
                    row[c * 8 + 4 + j] = co;
                }
            } else {
                for (int u = q; u < 12; u += 4) {
                    int c = u >> 2, j = u & 3;
                    row[c * 8 + j] = 0.f;
                    row[c * 8 + 4 + j] = 0.f;
                }
            }
        }
        __syncthreads();

        // ---- S5: hc = relu([As | Denc] @ Wc1 + bc1) -> Bs (stride HC_LD) ----
        {
            int R  = (tid >> 4) << 2;   // 0..60
            int C4 = (tid & 15) << 2;   // 0..60
            ull acc[4][2];
            #pragma unroll
            for (int i = 0; i < 4; i++) { acc[i][0] = 0ull; acc[i][1] = 0ull; }

            #pragma unroll 2
            for (int k = 0; k < 128; k++) {
                ulonglong2 bv = *reinterpret_cast<const ulonglong2*>(&Wc1s[k * 64 + C4]);
                #pragma unroll
                for (int i = 0; i < 4; i++) {
                    float a = As[(R + i) * ACT_LD + k];
                    ull ap = pack2(a, a);
                    fma2(acc[i][0], ap, bv.x);
                    fma2(acc[i][1], ap, bv.y);
                }
            }
            #pragma unroll 2
            for (int k = 0; k < 24; k++) {
                ulonglong2 bv = *reinterpret_cast<const ulonglong2*>(&Wc1s[(128 + k) * 64 + C4]);
                #pragma unroll
                for (int i = 0; i < 4; i++) {
                    float a = Denc[(R + i) * DENC_LD + k];
                    ull ap = pack2(a, a);
                    fma2(acc[i][0], ap, bv.x);
                    fma2(acc[i][1], ap, bv.y);
                }
            }
            #pragma unroll
            for (int i = 0; i < 4; i++)
                #pragma unroll
                for (int j = 0; j < 2; j++) {
                    float2 v = unpack2(acc[i][j]);
                    float lo = v.x + bc1s[C4 + 2 * j];
                    float hi = v.y + bc1s[C4 + 2 * j + 1];
                    lo = lo > 0.f ? lo : 0.f;
                    hi = hi > 0.f ? hi : 0.f;
                    *reinterpret_cast<float2*>(&Bs[(R + i) * HC_LD + C4 + 2 * j]) = make_float2(lo, hi);
                }
        }
        __syncthreads();

        // ---- S6: rgb + scatter (tid<64, sample = tid — FIXED index) ----
        {
            const int gs = m0 + tid;           // per-sample index for this stage
            if (tid < 64 && gs < cnt) {
                float r0 = bc20, r1 = bc21, r2 = bc22;
                const float* hrow = Bs + tid * HC_LD;
                #pragma unroll 4
                for (int k = 0; k < 64; k++) {
                    int k2 = (k + lane) & 63;
                    float h = hrow[k2];
                    r0 = fmaf(h, Wc2s[k2 * 3 + 0], r0);
                    r1 = fmaf(h, Wc2s[k2 * 3 + 1], r1);
                    r2 = fmaf(h, Wc2s[k2 * 3 + 2], r2);
                }
                float4 outv;
                outv.x = 1.0f / (1.0f + expf(-r0));
                outv.y = 1.0f / (1.0f + expf(-r1));
                outv.z = 1.0f / (1.0f + expf(-r2));
                outv.w = alpha[tid];
                *reinterpret_cast<float4*>(&g_rgba[g_sidx[gs] * 4]) = outv;
            }
        }
        __syncthreads();
    }
}

// ---------------- kernel 5: composite (register bitonic sort) ----------------
__global__ void __launch_bounds__(128) k_composite(float* __restrict__ out)
{
    int n = blockIdx.x * blockDim.x + threadIdx.x;
    if (n >= N_RAYS) return;

    float tv[N_PLANES];
    int   pv[N_PLANES];
    #pragma unroll
    for (int p = 0; p < N_PLANES; p++) {
        tv[p] = g_t[p * N_RAYS + n];
        pv[p] = p;
    }

    #pragma unroll
    for (int k = 2; k <= N_PLANES; k <<= 1) {
        #pragma unroll
        for (int j = k >> 1; j > 0; j >>= 1) {
            #pragma unroll
            for (int i = 0; i < N_PLANES; i++) {
                int l = i ^ j;
                if (l > i) {
                    bool up = ((i & k) == 0);
                    bool sw = up ? (tv[i] > tv[l]) : (tv[i] < tv[l]);
                    if (sw) {
                        float tt = tv[i]; tv[i] = tv[l]; tv[l] = tt;
                        int   pp = pv[i]; pv[i] = pv[l]; pv[l] = pp;
                    }
                }
            }
        }
    }

    float trans = 1.0f, sw = 0.0f, depth = 0.0f;
    float c0 = 0.f, c1 = 0.f, c2 = 0.f;
    #pragma unroll
    for (int s = 0; s < N_PLANES; s++) {
        int p = pv[s];
        float4 rg = *reinterpret_cast<const float4*>(&g_rgba[(p * N_RAYS + n) * 4]);
        float a = rg.w;
        float w = a * trans;
        depth = fmaf(tv[s], w, depth);
        c0 = fmaf(rg.x, w, c0);
        c1 = fmaf(rg.y, w, c1);
        c2 = fmaf(rg.z, w, c2);
        sw += w;
        trans *= (1.0f - a);
    }
    float bg = 1.0f - sw;
    out[n * 4 + 0] = c0 + bg;
    out[n * 4 + 1] = c1 + bg;
    out[n * 4 + 2] = c2 + bg;
    out[n * 4 + 3] = depth;
}

// ---------------- launch ----------------
extern "C" void kernel_launch(void* const* d_in, const int* in_sizes, int n_in,
                              void* d_out, int out_size)
{
    const float* ndc    = (const float*)d_in[0];
    const float* campos = (const float*)d_in[1];
    const float* camR   = (const float*)d_in[2];
    const float* basis  = (const float*)d_in[3];
    const float* center = (const float*)d_in[4];
    const float* wh     = (const float*)d_in[5];
    const float* W0     = (const float*)d_in[6];
    const float* b0     = (const float*)d_in[7];
    const float* W1     = (const float*)d_in[8];
    const float* b1     = (const float*)d_in[9];
    const float* Wa     = (const float*)d_in[10];
    const float* ba     = (const float*)d_in[11];
    const float* Wc1    = (const float*)d_in[12];
    const float* bc1    = (const float*)d_in[13];
    const float* Wc2    = (const float*)d_in[14];
    const float* bc2    = (const float*)d_in[15];
    float* out = (float*)d_out;

    static int smem_set = 0;
    if (!smem_set) {
        cudaFuncSetAttribute(k_mlp, cudaFuncAttributeMaxDynamicSharedMemorySize, SMEM_F);
        smem_set = 1;
    }

    k_reset<<<1, 32>>>();
    k_geom<<<NSAMP / 256, 256>>>(ndc, campos, camR, basis, center, wh);
    k_mlp<<<PERSIST_BLOCKS, 256, SMEM_F>>>(W0, b0, W1, b1, Wa, ba, Wc1, bc1, Wc2, bc2);
    k_composite<<<(N_RAYS + 127) / 128, 128>>>(out);
}

// round 8
// speedup vs baseline: 2.2110x; 1.4050x over previous
#include <cuda_runtime.h>
#include <cuda_bf16.h>
#include <mma.h>
#include <math.h>
#include <stdint.h>

using namespace nvcuda;

#define N_RAYS   32768
#define N_PLANES 32
#define NSAMP    (N_RAYS * N_PLANES)
#define EPSV     1e-8f
#define BM       64
#define PERSIST_BLOCKS 148
#define THREADS  256

// ---------------- scratch ----------------
__device__ int   g_cnt;
__device__ int   g_sidx[NSAMP];
__device__ float g_world[NSAMP * 3];
__device__ float g_vd[NSAMP * 3];
__device__ float g_t[NSAMP];
__device__ float g_rgba[NSAMP * 4];

// ---------------- kernel 0 ----------------
__global__ void k_reset() { if (threadIdx.x == 0) g_cnt = 0; }

// ---------------- kernel 1: geometry + compaction ----------------
__global__ void __launch_bounds__(256) k_geom(
    const float* __restrict__ ndc, const float* __restrict__ cam_pos,
    const float* __restrict__ cam_R, const float* __restrict__ basis,
    const float* __restrict__ center, const float* __restrict__ wh)
{
    int gid = blockIdx.x * blockDim.x + threadIdx.x;
    if (gid >= NSAMP) return;
    int p = gid / N_RAYS;
    int n = gid - p * N_RAYS;

    float nd0 = ndc[n * 3 + 0], nd1 = ndc[n * 3 + 1], nd2 = ndc[n * 3 + 2];
    float d0 = cam_R[0] * nd0 + cam_R[1] * nd1 + cam_R[2] * nd2;
    float d1 = cam_R[3] * nd0 + cam_R[4] * nd1 + cam_R[5] * nd2;
    float d2 = cam_R[6] * nd0 + cam_R[7] * nd1 + cam_R[8] * nd2;
    float o0 = cam_pos[0], o1 = cam_pos[1], o2 = cam_pos[2];

    const float* B = basis + p * 9;
    float pn0 = B[2], pn1 = B[5], pn2 = B[8];
    float c0 = center[p * 3 + 0], c1 = center[p * 3 + 1], c2 = center[p * 3 + 2];

    float denom = pn0 * d0 + pn1 * d1 + pn2 * d2;
    if (fabsf(denom) < EPSV) denom = EPSV;
    float num = (c0 - o0) * pn0 + (c1 - o1) * pn1 + (c2 - o2) * pn2;
    float t = num / denom;

    float w0 = o0 + t * d0, w1 = o1 + t * d1, w2 = o2 + t * d2;
    float u = (w0 - c0) * B[0] + (w1 - c1) * B[3] + (w2 - c2) * B[6];
    float v = (w0 - c0) * B[1] + (w1 - c1) * B[4] + (w2 - c2) * B[7];
    bool inside = (fabsf(u) <= wh[p * 2 + 0] * 0.5f) && (fabsf(v) <= wh[p * 2 + 1] * 0.5f);
    bool hit = inside && (t > 0.0f);

    g_t[gid] = t;

    unsigned mask = __ballot_sync(0xffffffffu, hit);
    if (hit) {
        int lane   = threadIdx.x & 31;
        int leader = __ffs(mask) - 1;
        int rank   = __popc(mask & ((1u << lane) - 1u));
        int base   = 0;
        if (lane == leader) base = atomicAdd(&g_cnt, __popc(mask));
        base = __shfl_sync(mask, base, leader);
        int i = base + rank;
        g_sidx[i] = gid;
        g_world[i * 3 + 0] = w0;
        g_world[i * 3 + 1] = w1;
        g_world[i * 3 + 2] = w2;
        float vd0 = w0 - o0, vd1 = w1 - o1, vd2 = w2 - o2;
        float inv = 1.0f / (sqrtf(vd0 * vd0 + vd1 * vd1 + vd2 * vd2) + EPSV);
        g_vd[i * 3 + 0] = vd0 * inv;
        g_vd[i * 3 + 1] = vd1 * inv;
        g_vd[i * 3 + 2] = vd2 * inv;
    } else {
        float4 z = make_float4(0.f, 0.f, 0.f, 0.f);
        *reinterpret_cast<float4*>(&g_rgba[gid * 4]) = z;
    }
}

// ---------------- fused persistent WMMA MLP ----------------
// leading dims (elements): odd multiples of 8 -> ldmatrix conflict-free
#define LDW  136   // W0/W1 (N=128 + pad)
#define LDWC 72    // Wc1  (N=64 + pad)
#define LDA  168   // activations (K up to 160 + pad)
#define LDC  132   // fp32 C scratch

// smem byte offsets (all 32B aligned)
#define SM_W0H   0
#define SM_W0L   (SM_W0H  + 64  * LDW  * 2)   // 17408
#define SM_W1H   (SM_W0L  + 64  * LDW  * 2)   // 34816
#define SM_W1L   (SM_W1H  + 128 * LDW  * 2)   // 69632
#define SM_WC1H  (SM_W1L  + 128 * LDW  * 2)   // 104448
#define SM_WC1L  (SM_WC1H + 160 * LDWC * 2)   // 127488
#define SM_AH    (SM_WC1L + 160 * LDWC * 2)   // 150528
#define SM_AL    (SM_AH   + 64  * LDA  * 2)   // 172032
#define SM_C     (SM_AL   + 64  * LDA  * 2)   // 193536
#define SM_SMALL (SM_C    + 64  * LDC  * 4)   // 227328
// small float arrays
#define SF_B0   0
#define SF_B1   128
#define SF_WA   256
#define SF_WC2  384
#define SF_BC1  576
#define SF_ALPHA 640
#define SF_END  704
#define SMEM_BYTES (SM_SMALL + SF_END * 4)    // 230144

typedef __nv_bfloat16 bf16;

__device__ __forceinline__ void split_bf16(float w, bf16& h, bf16& l) {
    h = __float2bfloat16(w);
    l = __float2bfloat16(w - __bfloat162float(h));
}

// stage a [Ksrc x N] row-major fp32 weight into hi/lo bf16 [Kpad x ld]
__device__ void stage_weight(const float* __restrict__ W, char* smem,
                             int hoff, int loff, int N, int Ksrc, int Kpad, int ld, int tid)
{
    for (int idx = tid; idx < Kpad * N; idx += THREADS) {
        int k = idx / N;
        int n = idx - k * N;
        float w = (k < Ksrc) ? W[k * N + n] : 0.0f;
        bf16 h, l; split_bf16(w, h, l);
        reinterpret_cast<bf16*>(smem + hoff)[k * ld + n] = h;
        reinterpret_cast<bf16*>(smem + loff)[k * ld + n] = l;
    }
}

// one layer GEMM with 2-term split: C[64 x N] = A[64 x K] @ B[K x N]
// NFRAG col-fragments per warp; cb = this warp's first col.
template <int KSTEPS, int NFRAG, int LDB>
__device__ __forceinline__ void wmma_layer(
    const bf16* Ah, const bf16* Al, const bf16* Bh, const bf16* Bl,
    float* C, int r16, int cb)
{
    wmma::fragment<wmma::accumulator, 16, 16, 16, float> acc[NFRAG];
    #pragma unroll
    for (int j = 0; j < NFRAG; j++) wmma::fill_fragment(acc[j], 0.0f);

    #pragma unroll
    for (int ks = 0; ks < KSTEPS; ks++) {
        wmma::fragment<wmma::matrix_a, 16, 16, 16, bf16, wmma::row_major> ah, al;
        wmma::load_matrix_sync(ah, Ah + r16 * LDA + ks * 16, LDA);
        wmma::load_matrix_sync(al, Al + r16 * LDA + ks * 16, LDA);
        #pragma unroll
        for (int j = 0; j < NFRAG; j++) {
            wmma::fragment<wmma::matrix_b, 16, 16, 16, bf16, wmma::row_major> bh, bl;
            wmma::load_matrix_sync(bh, Bh + ks * 16 * LDB + cb + j * 16, LDB);
            wmma::load_matrix_sync(bl, Bl + ks * 16 * LDB + cb + j * 16, LDB);
            wmma::mma_sync(acc[j], ah, bh, acc[j]);
            wmma::mma_sync(acc[j], ah, bl, acc[j]);
            wmma::mma_sync(acc[j], al, bh, acc[j]);
        }
    }
    #pragma unroll
    for (int j = 0; j < NFRAG; j++)
        wmma::store_matrix_sync(C + r16 * LDC + cb + j * 16, acc[j], LDC, wmma::mem_row_major);
}

__global__ void __launch_bounds__(THREADS, 1) k_mlp(
    const float* __restrict__ W0,  const float* __restrict__ b0,
    const float* __restrict__ W1,  const float* __restrict__ b1,
    const float* __restrict__ Wa,  const float* __restrict__ ba,
    const float* __restrict__ Wc1, const float* __restrict__ bc1,
    const float* __restrict__ Wc2, const float* __restrict__ bc2)
{
    extern __shared__ char smem[];
    bf16* W0h  = reinterpret_cast<bf16*>(smem + SM_W0H);
    bf16* W0l  = reinterpret_cast<bf16*>(smem + SM_W0L);
    bf16* W1h  = reinterpret_cast<bf16*>(smem + SM_W1H);
    bf16* W1l  = reinterpret_cast<bf16*>(smem + SM_W1L);
    bf16* Wc1h = reinterpret_cast<bf16*>(smem + SM_WC1H);
    bf16* Wc1l = reinterpret_cast<bf16*>(smem + SM_WC1L);
    bf16* Ah   = reinterpret_cast<bf16*>(smem + SM_AH);
    bf16* Al   = reinterpret_cast<bf16*>(smem + SM_AL);
    float* Cs  = reinterpret_cast<float*>(smem + SM_C);
    float* smf = reinterpret_cast<float*>(smem + SM_SMALL);
    float* bias0 = smf + SF_B0;
    float* bias1 = smf + SF_B1;
    float* Was   = smf + SF_WA;
    float* Wc2s  = smf + SF_WC2;
    float* bc1s  = smf + SF_BC1;
    float* alpha = smf + SF_ALPHA;

    const int tid  = threadIdx.x;
    const int wid  = tid >> 5;
    const int r    = tid >> 2;       // sample row 0..63
    const int q    = tid & 3;        // quad id
    const int r16  = (wid >> 1) * 16;
    const int cb64 = (wid & 1) * 64;
    const int cb32 = (wid & 1) * 32;
    const float ba0  = ba[0];
    const float bc20 = bc2[0], bc21 = bc2[1], bc22 = bc2[2];

    // ---- one-time weight staging ----
    stage_weight(W0,  smem, SM_W0H,  SM_W0L,  128, 60,  64,  LDW,  tid);
    stage_weight(W1,  smem, SM_W1H,  SM_W1L,  128, 128, 128, LDW,  tid);
    stage_weight(Wc1, smem, SM_WC1H, SM_WC1L, 64,  152, 160, LDWC, tid);
    if (tid < 128) { bias0[tid] = b0[tid]; bias1[tid] = b1[tid]; Was[tid] = Wa[tid]; }
    if (tid < 192) Wc2s[tid] = Wc2[tid];
    if (tid < 64)  bc1s[tid] = bc1[tid];
    __syncthreads();

    const int cnt    = g_cnt;
    const int nTiles = (cnt + BM - 1) >> 6;

    for (int tile = blockIdx.x; tile < nTiles; tile += gridDim.x) {
        const int gi   = (tile << 6) + r;
        const bool live = gi < cnt;

        // ===== S1: positional encoding -> Ah/Al rows (cols 0..63) =====
        {
            bf16* rh = Ah + r * LDA;
            bf16* rl = Al + r * LDA;
            if (live) {
                const float* wp = &g_world[gi * 3];
                float x0 = wp[0], x1 = wp[1], x2 = wp[2];
                for (int u = q; u < 30; u += 4) {
                    int c = (u >= 20) ? 2 : (u >= 10 ? 1 : 0);
                    int j = u - c * 10;
                    float x = (c == 0) ? x0 : (c == 1 ? x1 : x2);
                    float s, co;
                    sincosf(x * (float)(1 << j), &s, &co);
                    bf16 h, l;
                    split_bf16(s, h, l);  rh[c * 20 + j] = h;      rl[c * 20 + j] = l;
                    split_bf16(co, h, l); rh[c * 20 + 10 + j] = h; rl[c * 20 + 10 + j] = l;
                }
            } else {
                for (int u = q; u < 30; u += 4) {
                    int c = (u >= 20) ? 2 : (u >= 10 ? 1 : 0);
                    int j = u - c * 10;
                    rh[c * 20 + j] = __float2bfloat16(0.f);      rl[c * 20 + j] = __float2bfloat16(0.f);
                    rh[c * 20 + 10 + j] = __float2bfloat16(0.f); rl[c * 20 + 10 + j] = __float2bfloat16(0.f);
                }
            }
            if (q == 0) {
                #pragma unroll
                for (int c = 60; c < 64; c++) { rh[c] = __float2bfloat16(0.f); rl[c] = __float2bfloat16(0.f); }
            }
        }
        __syncthreads();

        // ===== L0: C = enc @ W0 (K=64, N=128) =====
        wmma_layer<4, 4, LDW>(Ah, Al, W0h, W0l, Cs, r16, cb64);
        __syncthreads();

        // ===== L0 epilogue: h0 = relu(C + b0) -> Ah/Al cols 0..127 =====
        {
            const float* crow = Cs + r * LDC;
            bf16* rh = Ah + r * LDA;
            bf16* rl = Al + r * LDA;
            int c0i = q * 32;
            #pragma unroll
            for (int c = 0; c < 32; c++) {
                float v = crow[c0i + c] + bias0[c0i + c];
                v = v > 0.f ? v : 0.f;
                bf16 h, l; split_bf16(v, h, l);
                rh[c0i + c] = h; rl[c0i + c] = l;
            }
        }
        __syncthreads();

        // ===== L1: C = h0 @ W1 (K=128, N=128) =====
        wmma_layer<8, 4, LDW>(Ah, Al, W1h, W1l, Cs, r16, cb64);
        __syncthreads();

        // ===== L1 epilogue: h1 = relu(C + b1) -> Ah/Al cols 0..127; alpha; denc =====
        {
            const float* crow = Cs + r * LDC;
            bf16* rh = Ah + r * LDA;
            bf16* rl = Al + r * LDA;
            int c0i = q * 32;
            float aacc = 0.f;
            #pragma unroll
            for (int c = 0; c < 32; c++) {
                float v = crow[c0i + c] + bias1[c0i + c];
                v = v > 0.f ? v : 0.f;
                aacc = fmaf(v, Was[c0i + c], aacc);
                bf16 h, l; split_bf16(v, h, l);
                rh[c0i + c] = h; rl[c0i + c] = l;
            }
            aacc += __shfl_xor_sync(0xffffffffu, aacc, 1);
            aacc += __shfl_xor_sync(0xffffffffu, aacc, 2);
            if (q == 0) alpha[r] = 1.0f / (1.0f + expf(-(aacc + ba0)));

            // direction encoding -> cols 128..151, zero pad 152..159
            if (live) {
                const float* vp = &g_vd[gi * 3];
                float x0 = vp[0], x1 = vp[1], x2 = vp[2];
                for (int u = q; u < 12; u += 4) {
                    int c = u >> 2, j = u & 3;
                    float x = (c == 0) ? x0 : (c == 1 ? x1 : x2);
                    float s, co;
                    sincosf(x * (float)(1 << j), &s, &co);
                    bf16 h, l;
                    split_bf16(s, h, l);  rh[128 + c * 8 + j] = h;     rl[128 + c * 8 + j] = l;
                    split_bf16(co, h, l); rh[128 + c * 8 + 4 + j] = h; rl[128 + c * 8 + 4 + j] = l;
                }
            } else {
                for (int u = q; u < 12; u += 4) {
                    int c = u >> 2, j = u & 3;
                    rh[128 + c * 8 + j] = __float2bfloat16(0.f);     rl[128 + c * 8 + j] = __float2bfloat16(0.f);
                    rh[128 + c * 8 + 4 + j] = __float2bfloat16(0.f); rl[128 + c * 8 + 4 + j] = __float2bfloat16(0.f);
                }
            }
            if (q == 1) {
                #pragma unroll
                for (int c = 152; c < 160; c++) { rh[c] = __float2bfloat16(0.f); rl[c] = __float2bfloat16(0.f); }
            }
        }
        __syncthreads();

        // ===== Wc1: C = [h1 | denc] @ Wc1 (K=160, N=64) =====
        wmma_layer<10, 2, LDWC>(Ah, Al, Wc1h, Wc1l, Cs, r16, cb32);
        __syncthreads();

        // ===== final: hc = relu(C + bc1); rgb = sigmoid(hc @ Wc2 + bc2); scatter =====
        {
            const float* crow = Cs + r * LDC;
            int c0i = q * 16;
            float a0 = 0.f, a1 = 0.f, a2 = 0.f;
            #pragma unroll
            for (int c = 0; c < 16; c++) {
                float h = crow[c0i + c] + bc1s[c0i + c];
                h = h > 0.f ? h : 0.f;
                a0 = fmaf(h, Wc2s[(c0i + c) * 3 + 0], a0);
                a1 = fmaf(h, Wc2s[(c0i + c) * 3 + 1], a1);
                a2 = fmaf(h, Wc2s[(c0i + c) * 3 + 2], a2);
            }
            a0 += __shfl_xor_sync(0xffffffffu, a0, 1);
            a0 += __shfl_xor_sync(0xffffffffu, a0, 2);
            a1 += __shfl_xor_sync(0xffffffffu, a1, 1);
            a1 += __shfl_xor_sync(0xffffffffu, a1, 2);
            a2 += __shfl_xor_sync(0xffffffffu, a2, 1);
            a2 += __shfl_xor_sync(0xffffffffu, a2, 2);
            if (q == 0 && live) {
                float4 outv;
                outv.x = 1.0f / (1.0f + expf(-(a0 + bc20)));
                outv.y = 1.0f / (1.0f + expf(-(a1 + bc21)));
                outv.z = 1.0f / (1.0f + expf(-(a2 + bc22)));
                outv.w = alpha[r];
                *reinterpret_cast<float4*>(&g_rgba[g_sidx[gi] * 4]) = outv;
            }
        }
        __syncthreads();
    }
}

// ---------------- kernel 5: composite (register bitonic sort) ----------------
__global__ void __launch_bounds__(128) k_composite(float* __restrict__ out)
{
    int n = blockIdx.x * blockDim.x + threadIdx.x;
    if (n >= N_RAYS) return;

    float tv[N_PLANES];
    int   pv[N_PLANES];
    #pragma unroll
    for (int p = 0; p < N_PLANES; p++) {
        tv[p] = g_t[p * N_RAYS + n];
        pv[p] = p;
    }

    #pragma unroll
    for (int k = 2; k <= N_PLANES; k <<= 1) {
        #pragma unroll
        for (int j = k >> 1; j > 0; j >>= 1) {
            #pragma unroll
            for (int i = 0; i < N_PLANES; i++) {
                int l = i ^ j;
                if (l > i) {
                    bool up = ((i & k) == 0);
                    bool sw = up ? (tv[i] > tv[l]) : (tv[i] < tv[l]);
                    if (sw) {
                        float tt = tv[i]; tv[i] = tv[l]; tv[l] = tt;
                        int   pp = pv[i]; pv[i] = pv[l]; pv[l] = pp;
                    }
                }
            }
        }
    }

    float trans = 1.0f, sw = 0.0f, depth = 0.0f;
    float c0 = 0.f, c1 = 0.f, c2 = 0.f;
    #pragma unroll
    for (int s = 0; s < N_PLANES; s++) {
        int p = pv[s];
        float4 rg = *reinterpret_cast<const float4*>(&g_rgba[(p * N_RAYS + n) * 4]);
        float a = rg.w;
        float w = a * trans;
        depth = fmaf(tv[s], w, depth);
        c0 = fmaf(rg.x, w, c0);
        c1 = fmaf(rg.y, w, c1);
        c2 = fmaf(rg.z, w, c2);
        sw += w;
        trans *= (1.0f - a);
    }
    float bg = 1.0f - sw;
    out[n * 4 + 0] = c0 + bg;
    out[n * 4 + 1] = c1 + bg;
    out[n * 4 + 2] = c2 + bg;
    out[n * 4 + 3] = depth;
}

// ---------------- launch ----------------
extern "C" void kernel_launch(void* const* d_in, const int* in_sizes, int n_in,
                              void* d_out, int out_size)
{
    const float* ndc    = (const float*)d_in[0];
    const float* campos = (const float*)d_in[1];
    const float* camR   = (const float*)d_in[2];
    const float* basis  = (const float*)d_in[3];
    const float* center = (const float*)d_in[4];
    const float* wh     = (const float*)d_in[5];
    const float* W0     = (const float*)d_in[6];
    const float* b0     = (const float*)d_in[7];
    const float* W1     = (const float*)d_in[8];
    const float* b1     = (const float*)d_in[9];
    const float* Wa     = (const float*)d_in[10];
    const float* ba     = (const float*)d_in[11];
    const float* Wc1    = (const float*)d_in[12];
    const float* bc1    = (const float*)d_in[13];
    const float* Wc2    = (const float*)d_in[14];
    const float* bc2    = (const float*)d_in[15];
    float* out = (float*)d_out;

    static int smem_set = 0;
    if (!smem_set) {
        cudaFuncSetAttribute(k_mlp, cudaFuncAttributeMaxDynamicSharedMemorySize, SMEM_BYTES);
        smem_set = 1;
    }

    k_reset<<<1, 32>>>();
    k_geom<<<NSAMP / 256, 256>>>(ndc, campos, camR, basis, center, wh);
    k_mlp<<<PERSIST_BLOCKS, THREADS, SMEM_BYTES>>>(W0, b0, W1, b1, Wa, ba, Wc1, bc1, Wc2, bc2);
    k_composite<<<(N_RAYS + 127) / 128, 128>>>(out);
}